// round 8
// baseline (speedup 1.0000x reference)
#include <cuda_runtime.h>
#include <cstdint>

#define POOL 7
#define NUM_ROIS 512
#define IMG_W 128
#define CH 1024
#define N_CELLS (NUM_ROIS * POOL * POOL)   // 25088
#define F4C 256                            // float4 per corner vector (1024 ch)
#define CELL_BYTES 4096                    // one corner vector
#define CPB 16                             // cells per block (25088/16 = 1568 blocks)
#define NSTAGE 2                           // 2 x 16KB = 32KB dynamic smem (+24B static: legal)

__device__ int4   g_offs[N_CELLS];         // byte offsets of the 4 corner vectors
__device__ float4 g_wts[N_CELLS];          // bilinear weights

// ---------------- setup: one thread per cell ----------------
__global__ void roi_setup_kernel(const int* __restrict__ rois) {
    const int cell = blockIdx.x * blockDim.x + threadIdx.x;
    if (cell >= N_CELLS) return;

    const int roi = cell / (POOL * POOL);
    const int rem = cell - roi * (POOL * POOL);
    const int py  = rem / POOL;
    const int px  = rem - py * POOL;

    const int x = rois[roi * 4 + 0];
    const int y = rois[roi * 4 + 1];
    const int w = rois[roi * 4 + 2];
    const int h = rois[roi * 4 + 3];

    const float hf = (float)h;
    const float wf = (float)w;

    // half-pixel-center source coords, clamped (matches tf.image.resize bilinear)
    float ys = ((float)py + 0.5f) * hf * (1.0f / POOL) - 0.5f;
    float xs = ((float)px + 0.5f) * wf * (1.0f / POOL) - 0.5f;
    ys = fminf(fmaxf(ys, 0.0f), hf - 1.0f);
    xs = fminf(fmaxf(xs, 0.0f), wf - 1.0f);

    const int y0 = (int)floorf(ys);
    const int x0 = (int)floorf(xs);
    const int y1 = min(y0 + 1, h - 1);
    const int x1 = min(x0 + 1, w - 1);
    const float fy = ys - (float)y0;
    const float fx = xs - (float)x0;

    const int ay0 = y + y0, ay1 = y + y1;
    const int ax0 = x + x0, ax1 = x + x1;

    int4 off;
    off.x = (ay0 * IMG_W + ax0) * CELL_BYTES;
    off.y = (ay0 * IMG_W + ax1) * CELL_BYTES;
    off.z = (ay1 * IMG_W + ax0) * CELL_BYTES;
    off.w = (ay1 * IMG_W + ax1) * CELL_BYTES;
    g_offs[cell] = off;

    float4 wt;
    wt.x = (1.0f - fy) * (1.0f - fx);
    wt.y = (1.0f - fy) * fx;
    wt.z = fy * (1.0f - fx);
    wt.w = fy * fx;
    g_wts[cell] = wt;
}

static __device__ __forceinline__ uint32_t smem_u32(const void* p) {
    uint32_t a;
    asm("{ .reg .u64 t; cvta.to.shared.u64 t, %1; cvt.u32.u64 %0, t; }"
        : "=r"(a) : "l"(p));
    return a;
}

static __device__ __forceinline__ void mbar_wait(uint32_t mb, uint32_t parity) {
    asm volatile(
        "{\n\t"
        ".reg .pred P;\n\t"
        "W_%=:\n\t"
        "mbarrier.try_wait.parity.acquire.cta.shared::cta.b64 P, [%0], %1, 0x989680;\n\t"
        "@!P bra W_%=;\n\t"
        "}"
        :: "r"(mb), "r"(parity) : "memory");
}

static __device__ __forceinline__ void bulk_ld(uint32_t dst, const char* src,
                                               uint32_t mb) {
    asm volatile(
        "cp.async.bulk.shared::cluster.global.mbarrier::complete_tx::bytes "
        "[%0], [%1], %2, [%3];"
        :: "r"(dst), "l"(src), "r"((uint32_t)CELL_BYTES), "r"(mb)
        : "memory");
}

// ---------------- main: TMA-pipelined, 16 cells per block ----------------
__global__ __launch_bounds__(256)
void roi_pool_kernel(const float* __restrict__ img, float* __restrict__ out) {
    extern __shared__ float4 buf[];            // [NSTAGE][4 * F4C] = 32KB
    __shared__ uint64_t mbar[NSTAGE];

    const int tid   = threadIdx.x;
    const int cell0 = blockIdx.x * CPB;
    const char* imgb = (const char*)img;

    if (tid == 0) {
#pragma unroll
        for (int s = 0; s < NSTAGE; s++)
            asm volatile("mbarrier.init.shared.b64 [%0], 1;"
                         :: "r"(smem_u32(&mbar[s])) : "memory");
        asm volatile("fence.proxy.async.shared::cta;" ::: "memory");
    }
    __syncthreads();

    auto issue = [&](int i) {
        const int4 off = g_offs[cell0 + i];
        const int  s   = i & (NSTAGE - 1);
        const uint32_t dst = smem_u32(&buf[s * 4 * F4C]);
        const uint32_t mb  = smem_u32(&mbar[s]);
        asm volatile("mbarrier.arrive.expect_tx.shared.b64 _, [%0], %1;"
                     :: "r"(mb), "r"((uint32_t)(4 * CELL_BYTES)) : "memory");
        bulk_ld(dst,                  imgb + off.x, mb);
        bulk_ld(dst + 1 * CELL_BYTES, imgb + off.y, mb);
        bulk_ld(dst + 2 * CELL_BYTES, imgb + off.z, mb);
        bulk_ld(dst + 3 * CELL_BYTES, imgb + off.w, mb);
    };

    // prologue: prefetch cell 0
    if (tid == 0) issue(0);

    float4* o_base = (float4*)out + (size_t)cell0 * F4C + tid;

    for (int i = 0; i < CPB; i++) {
        // next cell's stage was last read in iteration i-1; the trailing
        // __syncthreads() of that iteration makes re-arming it safe here.
        if (tid == 0 && i + 1 < CPB) issue(i + 1);

        const float4 wt = g_wts[cell0 + i];       // independent of the wait
        const int s = i & (NSTAGE - 1);
        mbar_wait(smem_u32(&mbar[s]), (uint32_t)((i >> 1) & 1));

        const float4* cb = &buf[s * 4 * F4C];
        const float4 a = cb[0 * F4C + tid];
        const float4 b = cb[1 * F4C + tid];
        const float4 c = cb[2 * F4C + tid];
        const float4 d = cb[3 * F4C + tid];

        float4 r;
        r.x = a.x * wt.x + b.x * wt.y + c.x * wt.z + d.x * wt.w;
        r.y = a.y * wt.x + b.y * wt.y + c.y * wt.z + d.y * wt.w;
        r.z = a.z * wt.x + b.z * wt.y + c.z * wt.z + d.z * wt.w;
        r.w = a.w * wt.x + b.w * wt.y + c.w * wt.z + d.w * wt.w;
        __stcs(o_base + i * F4C, r);              // stream output past L2

        // all threads done reading stage s before it gets re-armed next iter
        __syncthreads();
    }
}

extern "C" void kernel_launch(void* const* d_in, const int* in_sizes, int n_in,
                              void* d_out, int out_size) {
    const float* img  = (const float*)d_in[0];
    const int*   rois = (const int*)d_in[1];
    float*       out  = (float*)d_out;

    roi_setup_kernel<<<(N_CELLS + 255) / 256, 256>>>(rois);
    roi_pool_kernel<<<N_CELLS / CPB, 256, NSTAGE * 4 * CELL_BYTES>>>(img, out);
}